// round 4
// baseline (speedup 1.0000x reference)
#include <cuda_runtime.h>
#include <math.h>

#define EPSV 1e-06f

struct Sim3 {
    float tx, ty, tz;
    float qx, qy, qz, qw;
    float s;
};

__device__ __forceinline__ Sim3 load_sim3(const float* __restrict__ p) {
    float4 a = *reinterpret_cast<const float4*>(p);
    float4 b = *reinterpret_cast<const float4*>(p + 4);
    Sim3 T;
    T.tx = a.x; T.ty = a.y; T.tz = a.z;
    T.qx = a.w; T.qy = b.x; T.qz = b.y; T.qw = b.z;
    T.s  = b.w;
    return T;
}

// fast atan2 for y >= 0; |error| ~1e-5 rad
__device__ __forceinline__ float fast_atan2_pos(float y, float x) {
    float ax = fabsf(x);
    float mn = fminf(ax, y);
    float mx = fmaxf(ax, y);
    float a  = __fdividef(mn, mx);
    float s  = a * a;
    float r  = fmaf(fmaf(fmaf(fmaf(0.0208351f, s, -0.0851330f), s,
                              0.1801410f), s, -0.3302995f), s, 0.9998660f) * a;
    if (y > ax)   r = 1.5707963268f - r;
    if (x < 0.0f) r = 3.1415926536f - r;
    return r;
}

__device__ __forceinline__ void quat_rotate(float qx, float qy, float qz, float qw,
                                            float vx, float vy, float vz,
                                            float& ox, float& oy, float& oz) {
    float ux = qy * vz - qz * vy;
    float uy = qz * vx - qx * vz;
    float uz = qx * vy - qy * vx;
    float wx = qy * uz - qz * uy;
    float wy = qz * ux - qx * uz;
    float wz = qx * uy - qy * ux;
    ox = vx + 2.0f * (qw * ux + wx);
    oy = vy + 2.0f * (qw * uy + wy);
    oz = vz + 2.0f * (qw * uz + wz);
}

__device__ __forceinline__ Sim3 sim3_inv(const Sim3& T) {
    Sim3 R;
    R.qx = -T.qx; R.qy = -T.qy; R.qz = -T.qz; R.qw = T.qw;
    R.s = __fdividef(1.0f, T.s);
    float rx, ry, rz;
    quat_rotate(R.qx, R.qy, R.qz, R.qw, T.tx, T.ty, T.tz, rx, ry, rz);
    R.tx = -R.s * rx; R.ty = -R.s * ry; R.tz = -R.s * rz;
    return R;
}

__device__ __forceinline__ Sim3 sim3_mul(const Sim3& A, const Sim3& B) {
    Sim3 R;
    float rx, ry, rz;
    quat_rotate(A.qx, A.qy, A.qz, A.qw, B.tx, B.ty, B.tz, rx, ry, rz);
    R.tx = A.tx + A.s * rx;
    R.ty = A.ty + A.s * ry;
    R.tz = A.tz + A.s * rz;
    float x1 = A.qx, y1 = A.qy, z1 = A.qz, w1 = A.qw;
    float x2 = B.qx, y2 = B.qy, z2 = B.qz, w2 = B.qw;
    R.qx = w1 * x2 + x1 * w2 + y1 * z2 - z1 * y2;
    R.qy = w1 * y2 - x1 * z2 + y1 * w2 + z1 * x2;
    R.qz = w1 * z2 + x1 * y2 - y1 * x2 + z1 * w2;
    R.qw = w1 * w2 - x1 * x2 - y1 * y2 - z1 * z2;
    R.s = A.s * B.s;
    return R;
}

// out[7] = [tau(3), phi(3), sigma]
__device__ __forceinline__ void sim3_log(const Sim3& T, float out[7]) {
    float nv2 = T.qx * T.qx + T.qy * T.qy + T.qz * T.qz;
    float nv = (nv2 > 0.0f) ? nv2 * __frsqrt_rn(nv2) : 0.0f;
    float theta_r = 2.0f * fast_atan2_pos(nv, T.qw);
    bool small_r = nv < EPSV;
    float fac = small_r ? 2.0f : __fdividef(theta_r, nv);
    float px = fac * T.qx, py = fac * T.qy, pz = fac * T.qz;

    float sigma = __logf(T.s);
    // ||phi|| == fac * nv exactly (fac >= 0, nv >= 0)
    float theta = fac * nv;

    bool sig_small = fabsf(sigma) < EPSV;
    bool th_small  = theta < EPSV;

    float scale = __expf(sigma);
    float A, B, C;

    if (!(sig_small || th_small)) {
        // common path (measure-1 for random inputs)
        float th = theta, sg = sigma;
        float th2 = th * th, sg2 = sg * sg;
        float sth, cth;
        __sincosf(th, &sth, &cth);
        C = __fdividef(scale - 1.0f, sg);
        float c = th2 + sg2;
        float inv_c  = __fdividef(1.0f, c);
        float inv_th = __fdividef(1.0f, th);
        float inv_th2 = inv_th * inv_th;
        float a = scale * sth;
        float b = scale * cth;
        A = (a * sg + (1.0f - b) * th) * inv_th * inv_c;
        B = (C - ((b - 1.0f) * sg + a * th) * inv_c) * inv_th2;
    } else {
        // rare special-case path (reference select semantics)
        float sg = sig_small ? 1.0f : sigma;
        float th = th_small ? 1.0f : theta;
        float th2 = th * th, sg2 = sg * sg;
        float sth, cth;
        __sincosf(th, &sth, &cth);
        C = sig_small ? 1.0f : __fdividef(scale - 1.0f, sg);
        if (sig_small) {
            A = th_small ? 0.5f : __fdividef(1.0f - cth, th2);
            B = th_small ? (1.0f / 6.0f) : __fdividef(th - sth, th2 * th);
        } else {  // th_small, !sig_small
            A = __fdividef((sg - 1.0f) * scale + 1.0f, sg2);
            B = __fdividef(scale * (sg2 - 2.0f * sg + 2.0f) - 2.0f, 2.0f * sg2 * sg);
        }
    }

    // W = C*I + A*Phi + B*Phi^2
    float xx = px * px, yy = py * py, zz = pz * pz;
    float xy = px * py, xz = px * pz, yz = py * pz;

    float w00 = C - B * (yy + zz);
    float w01 = -A * pz + B * xy;
    float w02 =  A * py + B * xz;
    float w10 =  A * pz + B * xy;
    float w11 = C - B * (xx + zz);
    float w12 = -A * px + B * yz;
    float w20 = -A * py + B * xz;
    float w21 =  A * px + B * yz;
    float w22 = C - B * (xx + yy);

    // Cramer solve W * tau = t
    float m00 = w11 * w22 - w12 * w21;
    float m01 = w12 * w20 - w10 * w22;
    float m02 = w10 * w21 - w11 * w20;
    float det = w00 * m00 + w01 * m01 + w02 * m02;
    float invdet = __fdividef(1.0f, det);

    float m10 = w02 * w21 - w01 * w22;
    float m11 = w00 * w22 - w02 * w20;
    float m12 = w01 * w20 - w00 * w21;
    float m20 = w01 * w12 - w02 * w11;
    float m21 = w02 * w10 - w00 * w12;
    float m22 = w00 * w11 - w01 * w10;

    float tx = T.tx, ty = T.ty, tz = T.tz;
    out[0] = (m00 * tx + m10 * ty + m20 * tz) * invdet;
    out[1] = (m01 * tx + m11 * ty + m21 * tz) * invdet;
    out[2] = (m02 * tx + m12 * ty + m22 * tz) * invdet;
    out[3] = px;
    out[4] = py;
    out[5] = pz;
    out[6] = sigma;
}

__global__ __launch_bounds__(256, 5)
void pgo_kernel(const float* __restrict__ Twc,
                const float* __restrict__ Twc_prior_inv,
                const float* __restrict__ Todom_inv,
                const float* __restrict__ prior_weight,
                const float* __restrict__ odom_weight,
                const int*   __restrict__ edges,
                const float* __restrict__ T_lc,
                float* __restrict__ out,
                int n) {
    int i = blockIdx.x * blockDim.x + threadIdx.x;
    if (i >= n) return;

    // Issue the random gather chain EARLY (long latency)...
    int2 e = *reinterpret_cast<const int2*>(edges + 2 * (size_t)i);
    Sim3 Ta = load_sim3(Twc + 8 * (size_t)e.x);
    Sim3 Tb = load_sim3(Twc + 8 * (size_t)e.y);
    Sim3 Tl = load_sim3(T_lc + 8 * (size_t)i);

    // ...and overlap it with the prior-term math.
    Sim3 Ti  = load_sim3(Twc + 8 * (size_t)i);
    Sim3 Tj  = load_sim3(Twc + 8 * (size_t)(i + 1));
    Sim3 delta = sim3_mul(sim3_inv(Ti), Tj);

    float acc[7];
    {
        float r[7];
        Sim3 Tp = load_sim3(Twc_prior_inv + 8 * (size_t)i);
        sim3_log(sim3_mul(delta, Tp), r);
        const float* pw = prior_weight + 7 * (size_t)i;
        #pragma unroll
        for (int k = 0; k < 7; k++) acc[k] = r[k] * pw[k];
    }

    // Consume the gather now (latency hidden by the log above); frees Ta/Tb regs.
    {
        float r[7];
        Sim3 delta_lc = sim3_mul(sim3_inv(Ta), Tb);
        sim3_log(sim3_mul(delta_lc, Tl), r);
        #pragma unroll
        for (int k = 0; k < 7; k++) acc[k] += r[k];
    }

    {
        float r[7];
        Sim3 To = load_sim3(Todom_inv + 8 * (size_t)i);
        sim3_log(sim3_mul(delta, To), r);
        const float* ow = odom_weight + 7 * (size_t)i;
        #pragma unroll
        for (int k = 0; k < 7; k++) acc[k] = fmaf(r[k], ow[k], acc[k]);
    }

    float* o = out + 7 * (size_t)i;
    #pragma unroll
    for (int k = 0; k < 7; k++) o[k] = acc[k];
}

extern "C" void kernel_launch(void* const* d_in, const int* in_sizes, int n_in,
                              void* d_out, int out_size) {
    const float* Twc           = (const float*)d_in[0];
    const float* Twc_prior_inv = (const float*)d_in[1];
    const float* Todom_inv     = (const float*)d_in[2];
    const float* prior_weight  = (const float*)d_in[3];
    const float* odom_weight   = (const float*)d_in[4];
    const int*   edges         = (const int*)d_in[5];
    const float* T_lc          = (const float*)d_in[6];
    float* out = (float*)d_out;

    int n = out_size / 7;

    int threads = 256;
    int blocks = (n + threads - 1) / threads;
    pgo_kernel<<<blocks, threads>>>(Twc, Twc_prior_inv, Todom_inv,
                                    prior_weight, odom_weight, edges, T_lc,
                                    out, n);
}

// round 5
// speedup vs baseline: 1.0870x; 1.0870x over previous
#include <cuda_runtime.h>
#include <math.h>

#define EPSV 1e-06f

struct Sim3 {
    float tx, ty, tz;
    float qx, qy, qz, qw;
    float s;
};

__device__ __forceinline__ Sim3 load_sim3(const float* __restrict__ p) {
    float4 a = *reinterpret_cast<const float4*>(p);
    float4 b = *reinterpret_cast<const float4*>(p + 4);
    Sim3 T;
    T.tx = a.x; T.ty = a.y; T.tz = a.z;
    T.qx = a.w; T.qy = b.x; T.qz = b.y; T.qw = b.z;
    T.s  = b.w;
    return T;
}

// fast atan2 for y >= 0; |error| ~1e-5 rad
__device__ __forceinline__ float fast_atan2_pos(float y, float x) {
    float ax = fabsf(x);
    float mn = fminf(ax, y);
    float mx = fmaxf(ax, y);
    float a  = __fdividef(mn, mx);
    float s  = a * a;
    float r  = fmaf(fmaf(fmaf(fmaf(0.0208351f, s, -0.0851330f), s,
                              0.1801410f), s, -0.3302995f), s, 0.9998660f) * a;
    if (y > ax)   r = 1.5707963268f - r;
    if (x < 0.0f) r = 3.1415926536f - r;
    return r;
}

__device__ __forceinline__ void quat_rotate(float qx, float qy, float qz, float qw,
                                            float vx, float vy, float vz,
                                            float& ox, float& oy, float& oz) {
    float ux = qy * vz - qz * vy;
    float uy = qz * vx - qx * vz;
    float uz = qx * vy - qy * vx;
    float wx = qy * uz - qz * uy;
    float wy = qz * ux - qx * uz;
    float wz = qx * uy - qy * ux;
    ox = vx + 2.0f * (qw * ux + wx);
    oy = vy + 2.0f * (qw * uy + wy);
    oz = vz + 2.0f * (qw * uz + wz);
}

// Fused sim3_mul(sim3_inv(T1), T2):
//   q = conj(q1) * q2
//   s = s2 / s1
//   t = (1/s1) * R(conj(q1)) * (t2 - t1)
__device__ __forceinline__ Sim3 sim3_inv_mul(const Sim3& T1, const Sim3& T2) {
    float cx = -T1.qx, cy = -T1.qy, cz = -T1.qz, cw = T1.qw;
    float s_inv = __fdividef(1.0f, T1.s);

    float dx = T2.tx - T1.tx;
    float dy = T2.ty - T1.ty;
    float dz = T2.tz - T1.tz;
    float rx, ry, rz;
    quat_rotate(cx, cy, cz, cw, dx, dy, dz, rx, ry, rz);

    Sim3 R;
    R.tx = s_inv * rx; R.ty = s_inv * ry; R.tz = s_inv * rz;
    float x2 = T2.qx, y2 = T2.qy, z2 = T2.qz, w2 = T2.qw;
    R.qx = cw * x2 + cx * w2 + cy * z2 - cz * y2;
    R.qy = cw * y2 - cx * z2 + cy * w2 + cz * x2;
    R.qz = cw * z2 + cx * y2 - cy * x2 + cz * w2;
    R.qw = cw * w2 - cx * x2 - cy * y2 - cz * z2;
    R.s = s_inv * T2.s;
    return R;
}

__device__ __forceinline__ Sim3 sim3_mul(const Sim3& A, const Sim3& B) {
    Sim3 R;
    float rx, ry, rz;
    quat_rotate(A.qx, A.qy, A.qz, A.qw, B.tx, B.ty, B.tz, rx, ry, rz);
    R.tx = A.tx + A.s * rx;
    R.ty = A.ty + A.s * ry;
    R.tz = A.tz + A.s * rz;
    float x1 = A.qx, y1 = A.qy, z1 = A.qz, w1 = A.qw;
    float x2 = B.qx, y2 = B.qy, z2 = B.qz, w2 = B.qw;
    R.qx = w1 * x2 + x1 * w2 + y1 * z2 - z1 * y2;
    R.qy = w1 * y2 - x1 * z2 + y1 * w2 + z1 * x2;
    R.qz = w1 * z2 + x1 * y2 - y1 * x2 + z1 * w2;
    R.qw = w1 * w2 - x1 * x2 - y1 * y2 - z1 * z2;
    R.s = A.s * B.s;
    return R;
}

// out[7] = [tau(3), phi(3), sigma]
__device__ __forceinline__ void sim3_log(const Sim3& T, float out[7]) {
    float nv2 = T.qx * T.qx + T.qy * T.qy + T.qz * T.qz;
    float nv = (nv2 > 0.0f) ? nv2 * __frsqrt_rn(nv2) : 0.0f;
    float theta_r = 2.0f * fast_atan2_pos(nv, T.qw);
    bool small_r = nv < EPSV;
    float fac = small_r ? 2.0f : __fdividef(theta_r, nv);
    float px = fac * T.qx, py = fac * T.qy, pz = fac * T.qz;

    float sigma = __logf(T.s);
    // ||phi|| == fac * nv exactly (fac >= 0, nv >= 0)
    float theta = fac * nv;

    bool sig_small = fabsf(sigma) < EPSV;
    bool th_small  = theta < EPSV;
    float sg = sig_small ? 1.0f : sigma;
    float th = th_small ? 1.0f : theta;

    float scale = __expf(sigma);
    float th2 = th * th;
    float sg2 = sg * sg;

    float C = sig_small ? 1.0f : __fdividef(scale - 1.0f, sg);

    float sth, cth;
    __sincosf(th, &sth, &cth);

    // shared reciprocals
    float c      = th2 + sg2;
    float inv_c  = __fdividef(1.0f, c);
    float inv_th = __fdividef(1.0f, th);
    float inv_th2 = inv_th * inv_th;

    float a = scale * sth;
    float b = scale * cth;
    float A_g = (a * sg + (1.0f - b) * th) * inv_th * inv_c;
    float B_g = (C - ((b - 1.0f) * sg + a * th) * inv_c) * inv_th2;
    float A_ss = th_small ? 0.5f : (1.0f - cth) * inv_th2;
    float B_ss = th_small ? (1.0f / 6.0f) : (th - sth) * inv_th2 * inv_th;
    float A_ts = __fdividef((sg - 1.0f) * scale + 1.0f, sg2);
    float B_ts = __fdividef(scale * (sg2 - 2.0f * sg + 2.0f) - 2.0f, 2.0f * sg2 * sg);

    float A = sig_small ? A_ss : (th_small ? A_ts : A_g);
    float B = sig_small ? B_ss : (th_small ? B_ts : B_g);

    // W = C*I + A*Phi + B*Phi^2
    float xx = px * px, yy = py * py, zz = pz * pz;
    float xy = px * py, xz = px * pz, yz = py * pz;

    float w00 = C - B * (yy + zz);
    float w01 = -A * pz + B * xy;
    float w02 =  A * py + B * xz;
    float w10 =  A * pz + B * xy;
    float w11 = C - B * (xx + zz);
    float w12 = -A * px + B * yz;
    float w20 = -A * py + B * xz;
    float w21 =  A * px + B * yz;
    float w22 = C - B * (xx + yy);

    // Cramer solve W * tau = t
    float m00 = w11 * w22 - w12 * w21;
    float m01 = w12 * w20 - w10 * w22;
    float m02 = w10 * w21 - w11 * w20;
    float det = w00 * m00 + w01 * m01 + w02 * m02;
    float invdet = __fdividef(1.0f, det);

    float m10 = w02 * w21 - w01 * w22;
    float m11 = w00 * w22 - w02 * w20;
    float m12 = w01 * w20 - w00 * w21;
    float m20 = w01 * w12 - w02 * w11;
    float m21 = w02 * w10 - w00 * w12;
    float m22 = w00 * w11 - w01 * w10;

    float tx = T.tx, ty = T.ty, tz = T.tz;
    out[0] = (m00 * tx + m10 * ty + m20 * tz) * invdet;
    out[1] = (m01 * tx + m11 * ty + m21 * tz) * invdet;
    out[2] = (m02 * tx + m12 * ty + m22 * tz) * invdet;
    out[3] = px;
    out[4] = py;
    out[5] = pz;
    out[6] = sigma;
}

__global__ __launch_bounds__(256)
void pgo_kernel(const float* __restrict__ Twc,
                const float* __restrict__ Twc_prior_inv,
                const float* __restrict__ Todom_inv,
                const float* __restrict__ prior_weight,
                const float* __restrict__ odom_weight,
                const int*   __restrict__ edges,
                const float* __restrict__ T_lc,
                float* __restrict__ out,
                int n) {
    int i = blockIdx.x * blockDim.x + threadIdx.x;
    if (i >= n) return;

    // issue the random gather first so its latency overlaps the math below
    int2 e = *reinterpret_cast<const int2*>(edges + 2 * (size_t)i);
    Sim3 Ta = load_sim3(Twc + 8 * (size_t)e.x);
    Sim3 Tb = load_sim3(Twc + 8 * (size_t)e.y);
    Sim3 Tl = load_sim3(T_lc + 8 * (size_t)i);

    Sim3 Ti  = load_sim3(Twc + 8 * (size_t)i);
    Sim3 Tj  = load_sim3(Twc + 8 * (size_t)(i + 1));
    Sim3 delta = sim3_inv_mul(Ti, Tj);

    float r_prior[7], r_odom[7], r_lc[7];

    Sim3 Tp = load_sim3(Twc_prior_inv + 8 * (size_t)i);
    sim3_log(sim3_mul(delta, Tp), r_prior);

    Sim3 To = load_sim3(Todom_inv + 8 * (size_t)i);
    sim3_log(sim3_mul(delta, To), r_odom);

    Sim3 delta_lc = sim3_inv_mul(Ta, Tb);
    sim3_log(sim3_mul(delta_lc, Tl), r_lc);

    const float* pw = prior_weight + 7 * (size_t)i;
    const float* ow = odom_weight + 7 * (size_t)i;
    float* o = out + 7 * (size_t)i;
    #pragma unroll
    for (int k = 0; k < 7; k++) {
        o[k] = fmaf(r_prior[k], pw[k], fmaf(r_odom[k], ow[k], r_lc[k]));
    }
}

extern "C" void kernel_launch(void* const* d_in, const int* in_sizes, int n_in,
                              void* d_out, int out_size) {
    const float* Twc           = (const float*)d_in[0];
    const float* Twc_prior_inv = (const float*)d_in[1];
    const float* Todom_inv     = (const float*)d_in[2];
    const float* prior_weight  = (const float*)d_in[3];
    const float* odom_weight   = (const float*)d_in[4];
    const int*   edges         = (const int*)d_in[5];
    const float* T_lc          = (const float*)d_in[6];
    float* out = (float*)d_out;

    int n = out_size / 7;

    int threads = 256;
    int blocks = (n + threads - 1) / threads;
    pgo_kernel<<<blocks, threads>>>(Twc, Twc_prior_inv, Todom_inv,
                                    prior_weight, odom_weight, edges, T_lc,
                                    out, n);
}

// round 6
// speedup vs baseline: 1.0934x; 1.0059x over previous
#include <cuda_runtime.h>
#include <math.h>

#define EPSV 1e-06f

struct Sim3 {
    float tx, ty, tz;
    float qx, qy, qz, qw;
    float s;
};

__device__ __forceinline__ Sim3 load_sim3(const float* __restrict__ p) {
    float4 a = *reinterpret_cast<const float4*>(p);
    float4 b = *reinterpret_cast<const float4*>(p + 4);
    Sim3 T;
    T.tx = a.x; T.ty = a.y; T.tz = a.z;
    T.qx = a.w; T.qy = b.x; T.qz = b.y; T.qw = b.z;
    T.s  = b.w;
    return T;
}

// fast atan2 for y >= 0; |error| ~1e-5 rad
__device__ __forceinline__ float fast_atan2_pos(float y, float x) {
    float ax = fabsf(x);
    float mn = fminf(ax, y);
    float mx = fmaxf(ax, y);
    float a  = __fdividef(mn, mx);
    float s  = a * a;
    float r  = fmaf(fmaf(fmaf(fmaf(0.0208351f, s, -0.0851330f), s,
                              0.1801410f), s, -0.3302995f), s, 0.9998660f) * a;
    if (y > ax)   r = 1.5707963268f - r;
    if (x < 0.0f) r = 3.1415926536f - r;
    return r;
}

__device__ __forceinline__ void quat_rotate(float qx, float qy, float qz, float qw,
                                            float vx, float vy, float vz,
                                            float& ox, float& oy, float& oz) {
    float ux = qy * vz - qz * vy;
    float uy = qz * vx - qx * vz;
    float uz = qx * vy - qy * vx;
    float wx = qy * uz - qz * uy;
    float wy = qz * ux - qx * uz;
    float wz = qx * uy - qy * ux;
    ox = vx + 2.0f * (qw * ux + wx);
    oy = vy + 2.0f * (qw * uy + wy);
    oz = vz + 2.0f * (qw * uz + wz);
}

// Fused sim3_mul(sim3_inv(T1), T2)
__device__ __forceinline__ Sim3 sim3_inv_mul(const Sim3& T1, const Sim3& T2) {
    float cx = -T1.qx, cy = -T1.qy, cz = -T1.qz, cw = T1.qw;
    float s_inv = __fdividef(1.0f, T1.s);

    float dx = T2.tx - T1.tx;
    float dy = T2.ty - T1.ty;
    float dz = T2.tz - T1.tz;
    float rx, ry, rz;
    quat_rotate(cx, cy, cz, cw, dx, dy, dz, rx, ry, rz);

    Sim3 R;
    R.tx = s_inv * rx; R.ty = s_inv * ry; R.tz = s_inv * rz;
    float x2 = T2.qx, y2 = T2.qy, z2 = T2.qz, w2 = T2.qw;
    R.qx = cw * x2 + cx * w2 + cy * z2 - cz * y2;
    R.qy = cw * y2 - cx * z2 + cy * w2 + cz * x2;
    R.qz = cw * z2 + cx * y2 - cy * x2 + cz * w2;
    R.qw = cw * w2 - cx * x2 - cy * y2 - cz * z2;
    R.s = s_inv * T2.s;
    return R;
}

__device__ __forceinline__ Sim3 sim3_mul(const Sim3& A, const Sim3& B) {
    Sim3 R;
    float rx, ry, rz;
    quat_rotate(A.qx, A.qy, A.qz, A.qw, B.tx, B.ty, B.tz, rx, ry, rz);
    R.tx = A.tx + A.s * rx;
    R.ty = A.ty + A.s * ry;
    R.tz = A.tz + A.s * rz;
    float x1 = A.qx, y1 = A.qy, z1 = A.qz, w1 = A.qw;
    float x2 = B.qx, y2 = B.qy, z2 = B.qz, w2 = B.qw;
    R.qx = w1 * x2 + x1 * w2 + y1 * z2 - z1 * y2;
    R.qy = w1 * y2 - x1 * z2 + y1 * w2 + z1 * x2;
    R.qz = w1 * z2 + x1 * y2 - y1 * x2 + z1 * w2;
    R.qw = w1 * w2 - x1 * x2 - y1 * y2 - z1 * z2;
    R.s = A.s * B.s;
    return R;
}

// out[7] = [tau(3), phi(3), sigma]
__device__ __forceinline__ void sim3_log(const Sim3& T, float out[7]) {
    float nv2 = T.qx * T.qx + T.qy * T.qy + T.qz * T.qz;
    float nv = (nv2 > 0.0f) ? nv2 * __frsqrt_rn(nv2) : 0.0f;
    float theta_r = 2.0f * fast_atan2_pos(nv, T.qw);
    bool small_r = nv < EPSV;
    float fac = small_r ? 2.0f : __fdividef(theta_r, nv);
    float px = fac * T.qx, py = fac * T.qy, pz = fac * T.qz;

    float sigma = __logf(T.s);
    // ||phi|| == fac * nv exactly (fac >= 0, nv >= 0)
    float theta = fac * nv;

    bool sig_small = fabsf(sigma) < EPSV;
    bool th_small  = theta < EPSV;
    float sg = sig_small ? 1.0f : sigma;
    float th = th_small ? 1.0f : theta;

    // scale = exp(log(s)) == s
    float scale = T.s;
    float th2 = th * th;
    float sg2 = sg * sg;

    float C = sig_small ? 1.0f : __fdividef(scale - 1.0f, sg);

    float sth, cth;
    __sincosf(th, &sth, &cth);

    float c      = th2 + sg2;
    float inv_c  = __fdividef(1.0f, c);
    float inv_th = __fdividef(1.0f, th);
    float inv_th2 = inv_th * inv_th;

    float a = scale * sth;
    float b = scale * cth;
    float A_g = (a * sg + (1.0f - b) * th) * inv_th * inv_c;
    float B_g = (C - ((b - 1.0f) * sg + a * th) * inv_c) * inv_th2;
    float A_ss = th_small ? 0.5f : (1.0f - cth) * inv_th2;
    float B_ss = th_small ? (1.0f / 6.0f) : (th - sth) * inv_th2 * inv_th;
    float A_ts = __fdividef((sg - 1.0f) * scale + 1.0f, sg2);
    float B_ts = __fdividef(scale * (sg2 - 2.0f * sg + 2.0f) - 2.0f, 2.0f * sg2 * sg);

    float A = sig_small ? A_ss : (th_small ? A_ts : A_g);
    float B = sig_small ? B_ss : (th_small ? B_ts : B_g);

    // Closed-form inverse of W = C*I + A*Phi + B*Phi^2 using Phi^3 = -|phi|^2 * Phi:
    //   W^-1 = x*I + y*Phi + z*Phi^2
    //   P = C - |phi|^2 * B,  det2 = P^2 + |phi|^2 * A^2
    //   x = 1/C,  y = -A/det2,  z = (A^2 - P*B) / (C*det2)
    float t2t = theta * theta;           // true |phi|^2
    float P = C - t2t * B;
    float det2 = P * P + t2t * (A * A);
    float invC = __fdividef(1.0f, C);
    float invd = __fdividef(1.0f, det2);
    float y = -A * invd;
    float z = (A * A - P * B) * invC * invd;

    float tx = T.tx, ty = T.ty, tz = T.tz;
    // u = phi x t
    float ux = py * tz - pz * ty;
    float uy = pz * tx - px * tz;
    float uz = px * ty - py * tx;
    // v = phi x u
    float vx = py * uz - pz * uy;
    float vy = pz * ux - px * uz;
    float vz = px * uy - py * ux;

    out[0] = invC * tx + y * ux + z * vx;
    out[1] = invC * ty + y * uy + z * vy;
    out[2] = invC * tz + y * uz + z * vz;
    out[3] = px;
    out[4] = py;
    out[5] = pz;
    out[6] = sigma;
}

__global__ __launch_bounds__(256)
void pgo_kernel(const float* __restrict__ Twc,
                const float* __restrict__ Twc_prior_inv,
                const float* __restrict__ Todom_inv,
                const float* __restrict__ prior_weight,
                const float* __restrict__ odom_weight,
                const int*   __restrict__ edges,
                const float* __restrict__ T_lc,
                float* __restrict__ out,
                int n) {
    int i = blockIdx.x * blockDim.x + threadIdx.x;
    if (i >= n) return;

    // issue the random gather first so its latency overlaps the math below
    int2 e = *reinterpret_cast<const int2*>(edges + 2 * (size_t)i);
    Sim3 Ta = load_sim3(Twc + 8 * (size_t)e.x);
    Sim3 Tb = load_sim3(Twc + 8 * (size_t)e.y);
    Sim3 Tl = load_sim3(T_lc + 8 * (size_t)i);

    Sim3 Ti  = load_sim3(Twc + 8 * (size_t)i);
    Sim3 Tj  = load_sim3(Twc + 8 * (size_t)(i + 1));
    Sim3 delta = sim3_inv_mul(Ti, Tj);

    float r_prior[7], r_odom[7], r_lc[7];

    Sim3 Tp = load_sim3(Twc_prior_inv + 8 * (size_t)i);
    sim3_log(sim3_mul(delta, Tp), r_prior);

    Sim3 To = load_sim3(Todom_inv + 8 * (size_t)i);
    sim3_log(sim3_mul(delta, To), r_odom);

    Sim3 delta_lc = sim3_inv_mul(Ta, Tb);
    sim3_log(sim3_mul(delta_lc, Tl), r_lc);

    const float* pw = prior_weight + 7 * (size_t)i;
    const float* ow = odom_weight + 7 * (size_t)i;
    float* o = out + 7 * (size_t)i;
    #pragma unroll
    for (int k = 0; k < 7; k++) {
        o[k] = fmaf(r_prior[k], pw[k], fmaf(r_odom[k], ow[k], r_lc[k]));
    }
}

extern "C" void kernel_launch(void* const* d_in, const int* in_sizes, int n_in,
                              void* d_out, int out_size) {
    const float* Twc           = (const float*)d_in[0];
    const float* Twc_prior_inv = (const float*)d_in[1];
    const float* Todom_inv     = (const float*)d_in[2];
    const float* prior_weight  = (const float*)d_in[3];
    const float* odom_weight   = (const float*)d_in[4];
    const int*   edges         = (const int*)d_in[5];
    const float* T_lc          = (const float*)d_in[6];
    float* out = (float*)d_out;

    int n = out_size / 7;

    int threads = 256;
    int blocks = (n + threads - 1) / threads;
    pgo_kernel<<<blocks, threads>>>(Twc, Twc_prior_inv, Todom_inv,
                                    prior_weight, odom_weight, edges, T_lc,
                                    out, n);
}